// round 1
// baseline (speedup 1.0000x reference)
#include <cuda_runtime.h>
#include <cuda_bf16.h>
#include <math.h>

// NT-Xent loss, fused. N=4096, D=256, 2N=8192, T=0.1.
//   z = concat(z1,z2); z_i <- z_i * sqrt(10)/max(||z_i||, eps)
//   sim_ij = z_i . z_j  (== normalized-dot / T)
//   loss_i = log( sum_{j != i} exp(sim_ij) ) - sim_{i, i^4096}
//   out = mean_i loss_i
// exp(-1e9) underflows to exactly 0 in fp32, so skipping j==i matches the
// reference's masked_fill bit-for-bit in effect.

#define NN   8192      // 2N rows
#define HN   4096      // N
#define DD   256       // feature dim
#define BM   128
#define BN   128
#define BK   8
#define SPLITS 16
#define TILES_PER_SPLIT ((NN / BN) / SPLITS)   // 4

// Scratch (device globals: no allocations allowed in kernel_launch)
__device__ float g_z[NN * DD];                  // normalized+scaled z  (8 MB)
__device__ float g_rowsumPartial[SPLITS * NN];  // per-split exp row sums
__device__ float g_posval[NN];                  // positive-pair logits
__device__ float g_lossPartial[32];             // block partial loss sums

// ---------------------------------------------------------------------------
// Kernel A: normalize each row and scale by sqrt(1/T) = sqrt(10).
// 8192 blocks x 64 threads; each thread handles one float4 (4 elems).
// ---------------------------------------------------------------------------
__global__ __launch_bounds__(64) void normalize_kernel(
    const float* __restrict__ z1, const float* __restrict__ z2)
{
    int row = blockIdx.x;
    const float* src = (row < HN) ? (z1 + (size_t)row * DD)
                                  : (z2 + (size_t)(row - HN) * DD);
    int t = threadIdx.x;  // 0..63
    float4 v = reinterpret_cast<const float4*>(src)[t];
    float ss = v.x * v.x + v.y * v.y + v.z * v.z + v.w * v.w;

    // reduce over 64 threads (2 warps)
    #pragma unroll
    for (int off = 16; off > 0; off >>= 1)
        ss += __shfl_down_sync(0xffffffffu, ss, off);
    __shared__ float wsum[2];
    if ((t & 31) == 0) wsum[t >> 5] = ss;
    __syncthreads();
    float total = wsum[0] + wsum[1];

    float scale = 3.1622776601683795f / fmaxf(sqrtf(total), 1e-12f);
    float4 o;
    o.x = v.x * scale; o.y = v.y * scale; o.z = v.z * scale; o.w = v.w * scale;
    reinterpret_cast<float4*>(g_z + (size_t)row * DD)[t] = o;
}

// ---------------------------------------------------------------------------
// Kernel B: fused tiled GEMM (sim tile) + exp row-sum epilogue.
// grid = (SPLITS, NN/BM). Each block: BM rows x (TILES_PER_SPLIT * BN) cols.
// Deterministic: unique writer per (split,row) partial and per posval entry.
// ---------------------------------------------------------------------------
__global__ __launch_bounds__(256, 2) void sim_kernel()
{
    const int s   = blockIdx.x;          // column split
    const int rt  = blockIdx.y;          // row tile
    const int row0 = rt * BM;

    const int tid = threadIdx.x;         // 0..255
    const int tx  = tid & 15;            // 0..15  -> 8 cols each
    const int ty  = tid >> 4;            // 0..15  -> 8 rows each

    __shared__ float As[BK][BM + 4];     // padded: conflict-free transposed stores
    __shared__ float Bs[BK][BN + 4];

    // cooperative load mapping: one float4 per thread per tile-chunk
    const int lrow  = tid >> 1;          // 0..127
    const int lcol4 = (tid & 1) * 4;     // 0 or 4

    float rowexp[8];
    #pragma unroll
    for (int i = 0; i < 8; ++i) rowexp[i] = 0.0f;

    for (int t = 0; t < TILES_PER_SPLIT; ++t) {
        const int col0 = (s * TILES_PER_SPLIT + t) * BN;

        float acc[8][8];
        #pragma unroll
        for (int i = 0; i < 8; ++i)
            #pragma unroll
            for (int j = 0; j < 8; ++j) acc[i][j] = 0.0f;

        for (int k0 = 0; k0 < DD; k0 += BK) {
            float4 av = *reinterpret_cast<const float4*>(
                &g_z[(size_t)(row0 + lrow) * DD + k0 + lcol4]);
            float4 bv = *reinterpret_cast<const float4*>(
                &g_z[(size_t)(col0 + lrow) * DD + k0 + lcol4]);
            As[lcol4 + 0][lrow] = av.x;
            As[lcol4 + 1][lrow] = av.y;
            As[lcol4 + 2][lrow] = av.z;
            As[lcol4 + 3][lrow] = av.w;
            Bs[lcol4 + 0][lrow] = bv.x;
            Bs[lcol4 + 1][lrow] = bv.y;
            Bs[lcol4 + 2][lrow] = bv.z;
            Bs[lcol4 + 3][lrow] = bv.w;
            __syncthreads();

            #pragma unroll
            for (int k = 0; k < BK; ++k) {
                float a[8], b[8];
                #pragma unroll
                for (int i = 0; i < 8; ++i) a[i] = As[k][ty * 8 + i];
                #pragma unroll
                for (int j = 0; j < 8; ++j) b[j] = Bs[k][tx * 8 + j];
                #pragma unroll
                for (int i = 0; i < 8; ++i)
                    #pragma unroll
                    for (int j = 0; j < 8; ++j)
                        acc[i][j] = fmaf(a[i], b[j], acc[i][j]);
            }
            __syncthreads();
        }

        // epilogue: exp-accumulate, skip diagonal, capture positive logit
        #pragma unroll
        for (int i = 0; i < 8; ++i) {
            const int row  = row0 + ty * 8 + i;
            const int pcol = row ^ HN;            // positive pair column
            #pragma unroll
            for (int j = 0; j < 8; ++j) {
                const int col = col0 + tx * 8 + j;
                const float v = acc[i][j];
                if (col != row) rowexp[i] += __expf(v);
                if (col == pcol) g_posval[row] = v;   // unique writer
            }
        }
    }

    // reduce rowexp across the 16 tx-threads sharing each row
    __shared__ float red[BM][17];
    #pragma unroll
    for (int i = 0; i < 8; ++i) red[ty * 8 + i][tx] = rowexp[i];
    __syncthreads();
    if (tid < BM) {
        float sum = 0.0f;
        #pragma unroll
        for (int x = 0; x < 16; ++x) sum += red[tid][x];
        g_rowsumPartial[(size_t)s * NN + row0 + tid] = sum;
    }
}

// ---------------------------------------------------------------------------
// Kernel C: per-row loss + block partial reduce. 32 blocks x 256 threads.
// ---------------------------------------------------------------------------
__global__ __launch_bounds__(256) void loss_reduce_kernel()
{
    const int row = blockIdx.x * 256 + threadIdx.x;
    float tot = 0.0f;
    #pragma unroll
    for (int s = 0; s < SPLITS; ++s) tot += g_rowsumPartial[(size_t)s * NN + row];
    float loss = __logf(tot) - g_posval[row];

    __shared__ float sm[256];
    sm[threadIdx.x] = loss;
    __syncthreads();
    #pragma unroll
    for (int off = 128; off > 0; off >>= 1) {
        if (threadIdx.x < off) sm[threadIdx.x] += sm[threadIdx.x + off];
        __syncthreads();
    }
    if (threadIdx.x == 0) g_lossPartial[blockIdx.x] = sm[0];
}

// ---------------------------------------------------------------------------
// Kernel D: final scalar.
// ---------------------------------------------------------------------------
__global__ void finalize_kernel(float* __restrict__ out)
{
    float v = g_lossPartial[threadIdx.x];   // 32 threads
    #pragma unroll
    for (int off = 16; off > 0; off >>= 1)
        v += __shfl_down_sync(0xffffffffu, v, off);
    if (threadIdx.x == 0) out[0] = v * (1.0f / (float)NN);
}

// ---------------------------------------------------------------------------
extern "C" void kernel_launch(void* const* d_in, const int* in_sizes, int n_in,
                              void* d_out, int out_size)
{
    (void)in_sizes; (void)n_in; (void)out_size;
    const float* z1 = (const float*)d_in[0];
    const float* z2 = (const float*)d_in[1];
    // d_in[2]/d_in[3] (labels) are unused by the reference forward.
    float* out = (float*)d_out;

    normalize_kernel<<<NN, 64>>>(z1, z2);
    dim3 grid(SPLITS, NN / BM);
    sim_kernel<<<grid, 256>>>();
    loss_reduce_kernel<<<32, 256>>>();
    finalize_kernel<<<1, 32>>>(out);
}

// round 4
// speedup vs baseline: 7.3308x; 7.3308x over previous
#include <cuda_runtime.h>
#include <cuda_bf16.h>
#include <math.h>
#include <stdint.h>

// NT-Xent loss via portable mma.sync (HMMA) bf16 GEMM. N=4096, D=256, 2N=8192.
// sim = (z/||z|| * sqrt(10)) @ (z/||z|| * sqrt(10))^T, bf16 inputs, fp32 accum.
// loss_i = log(sum_{j!=i} exp(sim_ij)) - sim_{i, i^4096};  out = mean_i loss_i.
// NOTE: tcgen05/TMEM are unusable here (harness compiles via compute_103 virtual
// arch; arch-specific PTX is rejected). mma.sync + cp.async are portable PTX.

#define NN 8192
#define HN 4096
#define DD 256
#define TM 128
#define TN 128
#define NT 32               // col tiles per CTA (4096 / 128)

// ---- device scratch ----
__device__ __align__(512) __nv_bfloat16 g_zb[NN * DD];   // normalized z, bf16 (4 MB)
__device__ float g_rowsumPartial[2 * NN];
__device__ float g_posval[NN];
__device__ float g_lossPartial[32];

// ---------------------------------------------------------------------------
__device__ __forceinline__ uint32_t smem_u32(const void* p) {
    uint32_t a;
    asm("{ .reg .u64 t; cvta.to.shared.u64 t, %1; cvt.u32.u64 %0, t; }" : "=r"(a) : "l"(p));
    return a;
}
__device__ __forceinline__ void cp16(uint32_t smem_dst, const void* gsrc) {
    asm volatile("cp.async.cg.shared.global [%0], [%1], 16;" :: "r"(smem_dst), "l"(gsrc));
}
#define CP_COMMIT() asm volatile("cp.async.commit_group;" ::: "memory")
#define CP_WAIT0()  asm volatile("cp.async.wait_group 0;" ::: "memory")

__device__ __forceinline__ void ldsm_x4(uint32_t& r0, uint32_t& r1, uint32_t& r2,
                                        uint32_t& r3, uint32_t addr) {
    asm volatile("ldmatrix.sync.aligned.m8n8.x4.shared.b16 {%0,%1,%2,%3}, [%4];"
                 : "=r"(r0), "=r"(r1), "=r"(r2), "=r"(r3) : "r"(addr));
}
__device__ __forceinline__ void mma16816(float* c, const uint32_t* a, const uint32_t* b) {
    asm volatile(
        "mma.sync.aligned.m16n8k16.row.col.f32.bf16.bf16.f32 "
        "{%0,%1,%2,%3}, {%4,%5,%6,%7}, {%8,%9}, {%0,%1,%2,%3};"
        : "+f"(c[0]), "+f"(c[1]), "+f"(c[2]), "+f"(c[3])
        : "r"(a[0]), "r"(a[1]), "r"(a[2]), "r"(a[3]), "r"(b[0]), "r"(b[1]));
}

// ---------------------------------------------------------------------------
// Kernel A: normalize rows, scale by sqrt(10), emit bf16.
// ---------------------------------------------------------------------------
__global__ __launch_bounds__(64) void normalize_kernel(
    const float* __restrict__ z1, const float* __restrict__ z2)
{
    int row = blockIdx.x;
    const float* src = (row < HN) ? (z1 + (size_t)row * DD)
                                  : (z2 + (size_t)(row - HN) * DD);
    int t = threadIdx.x;
    float4 v = reinterpret_cast<const float4*>(src)[t];
    float ss = v.x * v.x + v.y * v.y + v.z * v.z + v.w * v.w;
    #pragma unroll
    for (int off = 16; off > 0; off >>= 1) ss += __shfl_down_sync(0xffffffffu, ss, off);
    __shared__ float wsum[2];
    if ((t & 31) == 0) wsum[t >> 5] = ss;
    __syncthreads();
    float total = wsum[0] + wsum[1];
    float scale = 3.1622776601683795f / fmaxf(sqrtf(total), 1e-12f);
    __nv_bfloat162* dst = reinterpret_cast<__nv_bfloat162*>(g_zb + (size_t)row * DD);
    dst[t * 2 + 0] = __floats2bfloat162_rn(v.x * scale, v.y * scale);
    dst[t * 2 + 1] = __floats2bfloat162_rn(v.z * scale, v.w * scale);
}

// ---------------------------------------------------------------------------
// Kernel B: HMMA GEMM + fused exp epilogue.
// grid = (64 row-tiles, 2 col-halves), 256 threads (8 warps, 4x2 warp grid).
// SMEM: A[128x256] resident (64KB) + B double buffer (2x64KB) = 192KB.
// Layout: row-major, 512B rows of 32 16B-chunks; chunk index XOR (row&7).
// ---------------------------------------------------------------------------
__global__ __launch_bounds__(256, 1) void sim_mma_kernel()
{
    extern __shared__ char smem[];
    const uint32_t sb = smem_u32(smem);
    const uint32_t A_BASE = sb, B_BASE = sb + 65536, BSZ = 65536;

    const int tid = threadIdx.x, wid = tid >> 5, lid = tid & 31;
    const int wy = wid >> 1, wx = wid & 1;       // warp grid 4 (m) x 2 (n)
    const int my = wy * 32, nx = wx * 64;
    const int rowbase = blockIdx.x * TM;
    const int h = blockIdx.y;

    // ---- prologue: A tile + B tile 0 via cp.async ----
    for (int i = tid; i < 4096; i += 256) {           // 128 rows x 32 chunks
        int r = i >> 5, c = i & 31;
        cp16(A_BASE + r * 512 + ((c ^ (r & 7)) << 4),
             &g_zb[(size_t)(rowbase + r) * DD + c * 8]);
    }
    {
        int colbase = h * HN;
        for (int i = tid; i < 4096; i += 256) {
            int r = i >> 5, c = i & 31;
            cp16(B_BASE + r * 512 + ((c ^ (r & 7)) << 4),
                 &g_zb[(size_t)(colbase + r) * DD + c * 8]);
        }
    }
    CP_COMMIT();

    // per-lane ldmatrix address components
    const int sub = lid >> 3, lr = lid & 7;
    const int rowA0 = my + ((sub & 1) << 3) + lr;     // + 16*i
    const int cAoff = sub >> 1;
    const int rowB0 = nx + ((sub >> 1) << 3) + lr;    // + 16*jj
    const int cBoff = sub & 1;

    float re[4] = {0.f, 0.f, 0.f, 0.f};               // per-lane exp row sums

    for (int t = 0; t < NT; ++t) {
        CP_WAIT0();
        __syncthreads();
        if (t + 1 < NT) {                              // prefetch next B tile
            uint32_t dstB = B_BASE + ((t + 1) & 1) * BSZ;
            int colbase = h * HN + (t + 1) * TN;
            for (int i = tid; i < 4096; i += 256) {
                int r = i >> 5, c = i & 31;
                cp16(dstB + r * 512 + ((c ^ (r & 7)) << 4),
                     &g_zb[(size_t)(colbase + r) * DD + c * 8]);
            }
            CP_COMMIT();
        }

        const uint32_t Bb = B_BASE + (t & 1) * BSZ;
        float acc[2][8][4];
        #pragma unroll
        for (int i = 0; i < 2; ++i)
            #pragma unroll
            for (int j = 0; j < 8; ++j)
                #pragma unroll
                for (int q = 0; q < 4; ++q) acc[i][j][q] = 0.f;

        #pragma unroll
        for (int ks = 0; ks < 16; ++ks) {
            const int c0 = 2 * ks;
            uint32_t a[2][4], b[8][2];
            #pragma unroll
            for (int i = 0; i < 2; ++i) {
                int row = rowA0 + 16 * i;
                ldsm_x4(a[i][0], a[i][1], a[i][2], a[i][3],
                        A_BASE + row * 512 + (((c0 + cAoff) ^ (row & 7)) << 4));
            }
            #pragma unroll
            for (int jj = 0; jj < 4; ++jj) {
                int row = rowB0 + 16 * jj;
                ldsm_x4(b[2 * jj][0], b[2 * jj][1], b[2 * jj + 1][0], b[2 * jj + 1][1],
                        Bb + row * 512 + (((c0 + cBoff) ^ (row & 7)) << 4));
            }
            #pragma unroll
            for (int i = 0; i < 2; ++i)
                #pragma unroll
                for (int j = 0; j < 8; ++j)
                    mma16816(acc[i][j], a[i], b[j]);
        }

        // ---- fused epilogue: exp row-sum (skip diag), capture positive ----
        const int colT = h * HN + t * TN + nx + 2 * (lid & 3);
        #pragma unroll
        for (int i = 0; i < 2; ++i) {
            const int gr0 = rowbase + my + 16 * i + (lid >> 2);
            const int gr1 = gr0 + 8;
            const int p0 = gr0 ^ HN, p1 = gr1 ^ HN;
            #pragma unroll
            for (int j = 0; j < 8; ++j) {
                const int gc0 = colT + 8 * j, gc1 = gc0 + 1;
                float v0 = acc[i][j][0], v1 = acc[i][j][1];
                float v2 = acc[i][j][2], v3 = acc[i][j][3];
                if (gc0 != gr0) re[2 * i]     += __expf(v0);
                if (gc1 != gr0) re[2 * i]     += __expf(v1);
                if (gc0 != gr1) re[2 * i + 1] += __expf(v2);
                if (gc1 != gr1) re[2 * i + 1] += __expf(v3);
                if (gc0 == p0) g_posval[gr0] = v0;
                if (gc1 == p0) g_posval[gr0] = v1;
                if (gc0 == p1) g_posval[gr1] = v2;
                if (gc1 == p1) g_posval[gr1] = v3;
            }
        }
    }

    // ---- reduce row sums: lanes sharing a row (lid&3), then wx pairs ----
    #pragma unroll
    for (int e = 0; e < 4; ++e) {
        re[e] += __shfl_xor_sync(0xffffffffu, re[e], 1);
        re[e] += __shfl_xor_sync(0xffffffffu, re[e], 2);
    }
    __syncthreads();                         // A region dead -> reuse for reduce
    float* red = reinterpret_cast<float*>(smem);   // [2][128]
    if ((lid & 3) == 0) {
        #pragma unroll
        for (int e = 0; e < 4; ++e) {
            int rl = my + 16 * (e >> 1) + 8 * (e & 1) + (lid >> 2);
            red[wx * 128 + rl] = re[e];
        }
    }
    __syncthreads();
    if (tid < 128)
        g_rowsumPartial[(size_t)h * NN + rowbase + tid] = red[tid] + red[128 + tid];
}

// ---------------------------------------------------------------------------
__global__ __launch_bounds__(256) void loss_reduce_kernel()
{
    const int row = blockIdx.x * 256 + threadIdx.x;
    float tot = g_rowsumPartial[row] + g_rowsumPartial[NN + row];
    float loss = __logf(tot) - g_posval[row];

    __shared__ float sm[256];
    sm[threadIdx.x] = loss;
    __syncthreads();
    #pragma unroll
    for (int off = 128; off > 0; off >>= 1) {
        if (threadIdx.x < off) sm[threadIdx.x] += sm[threadIdx.x + off];
        __syncthreads();
    }
    if (threadIdx.x == 0) g_lossPartial[blockIdx.x] = sm[0];
}

__global__ void finalize_kernel(float* __restrict__ out)
{
    float v = g_lossPartial[threadIdx.x];
    #pragma unroll
    for (int off = 16; off > 0; off >>= 1) v += __shfl_down_sync(0xffffffffu, v, off);
    if (threadIdx.x == 0) out[0] = v * (1.0f / (float)NN);
}

// ---------------------------------------------------------------------------
extern "C" void kernel_launch(void* const* d_in, const int* in_sizes, int n_in,
                              void* d_out, int out_size)
{
    (void)in_sizes; (void)n_in; (void)out_size;
    const float* z1 = (const float*)d_in[0];
    const float* z2 = (const float*)d_in[1];
    float* out = (float*)d_out;

    static int smem_set = 0;
    const int SMEM_BYTES = 196608;
    if (!smem_set) {
        cudaFuncSetAttribute(sim_mma_kernel,
                             cudaFuncAttributeMaxDynamicSharedMemorySize, SMEM_BYTES);
        smem_set = 1;
    }

    normalize_kernel<<<NN, 64>>>(z1, z2);
    dim3 grid(NN / TM, 2);
    sim_mma_kernel<<<grid, 256, SMEM_BYTES>>>();
    loss_reduce_kernel<<<32, 256>>>();
    finalize_kernel<<<1, 32>>>(out);
}

// round 5
// speedup vs baseline: 7.4708x; 1.0191x over previous
#include <cuda_runtime.h>
#include <cuda_bf16.h>
#include <math.h>
#include <stdint.h>

// NT-Xent loss via portable mma.sync (HMMA) bf16 GEMM. N=4096, D=256, 2N=8192.
// z' = z/||z|| * sqrt(10*log2e)  (bf16)  =>  acc = z'_i.z'_j = sim_ij * log2(e)
// exp(sim_ij) = ex2(acc).  loss_i = ln2*( lg2(sum_{j!=i} ex2(acc_ij)) - acc_pos ).
// out = mean_i loss_i.

#define NN 8192
#define HN 4096
#define DD 256
#define TM 128
#define TN 128
#define NT 32                       // col tiles per CTA (4096 / 128)
#define C_SCALE 3.7982825615419297f // sqrt(10 * log2(e))
#define LN2 0.6931471805599453f

// ---- device scratch ----
__device__ __align__(512) __nv_bfloat16 g_zb[NN * DD];   // normalized z, bf16 (4 MB)
__device__ float g_rowsumPartial[2 * NN];
__device__ float g_posacc[NN];       // positive-pair logit, log2 domain
// ---------------------------------------------------------------------------
__device__ __forceinline__ uint32_t smem_u32(const void* p) {
    uint32_t a;
    asm("{ .reg .u64 t; cvta.to.shared.u64 t, %1; cvt.u32.u64 %0, t; }" : "=r"(a) : "l"(p));
    return a;
}
__device__ __forceinline__ void cp16(uint32_t smem_dst, const void* gsrc) {
    asm volatile("cp.async.cg.shared.global [%0], [%1], 16;" :: "r"(smem_dst), "l"(gsrc));
}
#define CP_COMMIT() asm volatile("cp.async.commit_group;" ::: "memory")
#define CP_WAIT0()  asm volatile("cp.async.wait_group 0;" ::: "memory")

__device__ __forceinline__ float ex2f(float x) {
    float y; asm("ex2.approx.f32 %0, %1;" : "=f"(y) : "f"(x)); return y;
}
__device__ __forceinline__ float lg2f(float x) {
    float y; asm("lg2.approx.f32 %0, %1;" : "=f"(y) : "f"(x)); return y;
}
__device__ __forceinline__ void ldsm_x4(uint32_t& r0, uint32_t& r1, uint32_t& r2,
                                        uint32_t& r3, uint32_t addr) {
    asm volatile("ldmatrix.sync.aligned.m8n8.x4.shared.b16 {%0,%1,%2,%3}, [%4];"
                 : "=r"(r0), "=r"(r1), "=r"(r2), "=r"(r3) : "r"(addr));
}
__device__ __forceinline__ void mma16816(float* c, const uint32_t* a, const uint32_t* b) {
    asm volatile(
        "mma.sync.aligned.m16n8k16.row.col.f32.bf16.bf16.f32 "
        "{%0,%1,%2,%3}, {%4,%5,%6,%7}, {%8,%9}, {%0,%1,%2,%3};"
        : "+f"(c[0]), "+f"(c[1]), "+f"(c[2]), "+f"(c[3])
        : "r"(a[0]), "r"(a[1]), "r"(a[2]), "r"(a[3]), "r"(b[0]), "r"(b[1]));
}

// ---------------------------------------------------------------------------
// Kernel A: normalize rows, scale by sqrt(10*log2e), emit bf16. Warp per row.
// ---------------------------------------------------------------------------
__global__ __launch_bounds__(256) void normalize_kernel(
    const float* __restrict__ z1, const float* __restrict__ z2)
{
    const int wid = threadIdx.x >> 5, lid = threadIdx.x & 31;
    const int row = blockIdx.x * 8 + wid;
    const float* src = (row < HN) ? (z1 + (size_t)row * DD)
                                  : (z2 + (size_t)(row - HN) * DD);
    float4 v0 = reinterpret_cast<const float4*>(src)[lid];
    float4 v1 = reinterpret_cast<const float4*>(src)[lid + 32];
    float ss = v0.x * v0.x + v0.y * v0.y + v0.z * v0.z + v0.w * v0.w
             + v1.x * v1.x + v1.y * v1.y + v1.z * v1.z + v1.w * v1.w;
    #pragma unroll
    for (int off = 16; off > 0; off >>= 1) ss += __shfl_xor_sync(0xffffffffu, ss, off);
    float s = C_SCALE / fmaxf(sqrtf(ss), 1e-12f);
    __nv_bfloat162* dst = reinterpret_cast<__nv_bfloat162*>(g_zb + (size_t)row * DD);
    dst[2 * lid + 0]      = __floats2bfloat162_rn(v0.x * s, v0.y * s);
    dst[2 * lid + 1]      = __floats2bfloat162_rn(v0.z * s, v0.w * s);
    dst[64 + 2 * lid + 0] = __floats2bfloat162_rn(v1.x * s, v1.y * s);
    dst[64 + 2 * lid + 1] = __floats2bfloat162_rn(v1.z * s, v1.w * s);
}

// ---------------------------------------------------------------------------
// Kernel B: HMMA GEMM + fused ex2 epilogue.
// grid = (64 row-tiles, 2 col-halves), 256 threads (8 warps, 4x2 warp grid).
// SMEM: A[128x256] resident (64KB) + B double buffer (2x64KB) = 192KB.
// Exactly ONE tile per CTA contains diag or pos elements:
//   t_spec = (rowbase & 4095) >> 7 ; diag iff (rowbase>>12)==h else pos.
// All other 31 tiles take a compare-free ex2+add fast path.
// ---------------------------------------------------------------------------
__global__ __launch_bounds__(256, 1) void sim_mma_kernel()
{
    extern __shared__ char smem[];
    const uint32_t sb = smem_u32(smem);
    const uint32_t A_BASE = sb, B_BASE = sb + 65536, BSZ = 65536;

    const int tid = threadIdx.x, wid = tid >> 5, lid = tid & 31;
    const int wy = wid >> 1, wx = wid & 1;       // warp grid 4 (m) x 2 (n)
    const int my = wy * 32, nx = wx * 64;
    const int rowbase = blockIdx.x * TM;
    const int h = blockIdx.y;
    const int t_spec  = (rowbase & 4095) >> 7;
    const int is_diag = ((rowbase >> 12) == h);

    // ---- prologue: A tile + B tile 0 via cp.async ----
    for (int i = tid; i < 4096; i += 256) {           // 128 rows x 32 chunks
        int r = i >> 5, c = i & 31;
        cp16(A_BASE + r * 512 + ((c ^ (r & 7)) << 4),
             &g_zb[(size_t)(rowbase + r) * DD + c * 8]);
    }
    {
        int colbase = h * HN;
        for (int i = tid; i < 4096; i += 256) {
            int r = i >> 5, c = i & 31;
            cp16(B_BASE + r * 512 + ((c ^ (r & 7)) << 4),
                 &g_zb[(size_t)(colbase + r) * DD + c * 8]);
        }
    }
    CP_COMMIT();

    // per-lane ldmatrix address components
    const int sub = lid >> 3, lr = lid & 7;
    const int rowA0 = my + ((sub & 1) << 3) + lr;     // + 16*i
    const int cAoff = sub >> 1;
    const int rowB0 = nx + ((sub >> 1) << 3) + lr;    // + 16*jj
    const int cBoff = sub & 1;

    float re[4] = {0.f, 0.f, 0.f, 0.f};               // per-lane exp row sums

    for (int t = 0; t < NT; ++t) {
        CP_WAIT0();
        __syncthreads();
        if (t + 1 < NT) {                              // prefetch next B tile
            uint32_t dstB = B_BASE + ((t + 1) & 1) * BSZ;
            int colbase = h * HN + (t + 1) * TN;
            for (int i = tid; i < 4096; i += 256) {
                int r = i >> 5, c = i & 31;
                cp16(dstB + r * 512 + ((c ^ (r & 7)) << 4),
                     &g_zb[(size_t)(colbase + r) * DD + c * 8]);
            }
            CP_COMMIT();
        }

        const uint32_t Bb = B_BASE + (t & 1) * BSZ;
        float acc[2][8][4];
        #pragma unroll
        for (int i = 0; i < 2; ++i)
            #pragma unroll
            for (int j = 0; j < 8; ++j)
                #pragma unroll
                for (int q = 0; q < 4; ++q) acc[i][j][q] = 0.f;

        #pragma unroll
        for (int ks = 0; ks < 16; ++ks) {
            const int c0 = 2 * ks;
            uint32_t a[2][4], b[8][2];
            #pragma unroll
            for (int i = 0; i < 2; ++i) {
                int row = rowA0 + 16 * i;
                ldsm_x4(a[i][0], a[i][1], a[i][2], a[i][3],
                        A_BASE + row * 512 + (((c0 + cAoff) ^ (row & 7)) << 4));
            }
            #pragma unroll
            for (int jj = 0; jj < 4; ++jj) {
                int row = rowB0 + 16 * jj;
                ldsm_x4(b[2 * jj][0], b[2 * jj][1], b[2 * jj + 1][0], b[2 * jj + 1][1],
                        Bb + row * 512 + (((c0 + cBoff) ^ (row & 7)) << 4));
            }
            #pragma unroll
            for (int i = 0; i < 2; ++i)
                #pragma unroll
                for (int j = 0; j < 8; ++j)
                    mma16816(acc[i][j], a[i], b[j]);
        }

        // ---- fused epilogue ----
        if (t != t_spec) {
            // fast path: no diag / no pos in this tile
            #pragma unroll
            for (int i = 0; i < 2; ++i)
                #pragma unroll
                for (int j = 0; j < 8; ++j) {
                    re[2 * i]     += ex2f(acc[i][j][0]) + ex2f(acc[i][j][1]);
                    re[2 * i + 1] += ex2f(acc[i][j][2]) + ex2f(acc[i][j][3]);
                }
        } else {
            const int colT = h * HN + t * TN + nx + 2 * (lid & 3);
            #pragma unroll
            for (int i = 0; i < 2; ++i) {
                const int gr0 = rowbase + my + 16 * i + (lid >> 2);
                const int gr1 = gr0 + 8;
                #pragma unroll
                for (int j = 0; j < 8; ++j) {
                    const int gc0 = colT + 8 * j, gc1 = gc0 + 1;
                    float v0 = acc[i][j][0], v1 = acc[i][j][1];
                    float v2 = acc[i][j][2], v3 = acc[i][j][3];
                    if (is_diag) {
                        if (gc0 != gr0) re[2 * i]     += ex2f(v0);
                        if (gc1 != gr0) re[2 * i]     += ex2f(v1);
                        if (gc0 != gr1) re[2 * i + 1] += ex2f(v2);
                        if (gc1 != gr1) re[2 * i + 1] += ex2f(v3);
                    } else {
                        re[2 * i]     += ex2f(v0) + ex2f(v1);
                        re[2 * i + 1] += ex2f(v2) + ex2f(v3);
                        const int p0 = gr0 ^ HN, p1 = gr1 ^ HN;
                        if (gc0 == p0) g_posacc[gr0] = v0;
                        if (gc1 == p0) g_posacc[gr0] = v1;
                        if (gc0 == p1) g_posacc[gr1] = v2;
                        if (gc1 == p1) g_posacc[gr1] = v3;
                    }
                }
            }
        }
    }

    // ---- reduce row sums: lanes sharing a row (lid&3), then wx pairs ----
    #pragma unroll
    for (int e = 0; e < 4; ++e) {
        re[e] += __shfl_xor_sync(0xffffffffu, re[e], 1);
        re[e] += __shfl_xor_sync(0xffffffffu, re[e], 2);
    }
    __syncthreads();                         // A region dead -> reuse for reduce
    float* red = reinterpret_cast<float*>(smem);   // [2][128]
    if ((lid & 3) == 0) {
        #pragma unroll
        for (int e = 0; e < 4; ++e) {
            int rl = my + 16 * (e >> 1) + 8 * (e & 1) + (lid >> 2);
            red[wx * 128 + rl] = re[e];
        }
    }
    __syncthreads();
    if (tid < 128)
        g_rowsumPartial[(size_t)h * NN + rowbase + tid] = red[tid] + red[128 + tid];
}

// ---------------------------------------------------------------------------
// Kernel C: per-row loss + full reduce to scalar. One block, 1024 threads.
// ---------------------------------------------------------------------------
__global__ __launch_bounds__(1024) void loss_kernel(float* __restrict__ out)
{
    float s = 0.f;
    for (int r = threadIdx.x; r < NN; r += 1024) {
        float tot = g_rowsumPartial[r] + g_rowsumPartial[NN + r];
        s += lg2f(tot) - g_posacc[r];
    }
    #pragma unroll
    for (int off = 16; off > 0; off >>= 1) s += __shfl_down_sync(0xffffffffu, s, off);
    __shared__ float w[32];
    if ((threadIdx.x & 31) == 0) w[threadIdx.x >> 5] = s;
    __syncthreads();
    if (threadIdx.x < 32) {
        float v = w[threadIdx.x];
        #pragma unroll
        for (int off = 16; off > 0; off >>= 1) v += __shfl_down_sync(0xffffffffu, v, off);
        if (threadIdx.x == 0) out[0] = v * (LN2 / (float)NN);
    }
}

// ---------------------------------------------------------------------------
extern "C" void kernel_launch(void* const* d_in, const int* in_sizes, int n_in,
                              void* d_out, int out_size)
{
    (void)in_sizes; (void)n_in; (void)out_size;
    const float* z1 = (const float*)d_in[0];
    const float* z2 = (const float*)d_in[1];
    float* out = (float*)d_out;

    static int smem_set = 0;
    const int SMEM_BYTES = 196608;
    if (!smem_set) {
        cudaFuncSetAttribute(sim_mma_kernel,
                             cudaFuncAttributeMaxDynamicSharedMemorySize, SMEM_BYTES);
        smem_set = 1;
    }

    normalize_kernel<<<NN / 8, 256>>>(z1, z2);
    dim3 grid(NN / TM, 2);
    sim_mma_kernel<<<grid, 256, SMEM_BYTES>>>();
    loss_kernel<<<1, 1024>>>(out);
}

// round 6
// speedup vs baseline: 10.7986x; 1.4455x over previous
#include <cuda_runtime.h>
#include <cuda_bf16.h>
#include <math.h>
#include <stdint.h>

// NT-Xent loss via symmetric-triangle HMMA bf16 GEMM. N=4096, D=256, 2N=8192.
// z' = z/||z|| * sqrt(10*log2e) (bf16) => acc = sim_ij * log2(e).
// sim symmetric => compute only tiles (I,J) with I<=J; each off-diag tile
// contributes row sums (block I) and column sums (block J, by symmetry).
// loss_i = ln2*( lg2(sum_{j!=i} ex2(acc_ij)) - acc_pos ); out = mean.

#define NN 8192
#define HN 4096
#define DD 256
#define NBLK 64                     // 8192 / 128 row blocks
#define NFLAT 2080                  // 64*65/2 tiles
#define NCTA 130                    // 2080 / 16
#define TPC 16                      // tiles per CTA
#define C_SCALE 3.7982825615419297f // sqrt(10 * log2(e))
#define LN2 0.6931471805599453f

// ---- device scratch ----
__device__ __align__(512) __nv_bfloat16 g_zb[NN * DD];   // normalized z (4 MB)
__device__ float g_rowPart[NFLAT * 128];
__device__ float g_colPart[NFLAT * 128];
__device__ float g_posacc[NN];
__device__ float g_lossPartial[32];
__device__ int   g_ctr = 0;          // reset by finalizing block each launch

// ---------------------------------------------------------------------------
__device__ __forceinline__ uint32_t smem_u32(const void* p) {
    uint32_t a;
    asm("{ .reg .u64 t; cvta.to.shared.u64 t, %1; cvt.u32.u64 %0, t; }" : "=r"(a) : "l"(p));
    return a;
}
__device__ __forceinline__ void cp16(uint32_t smem_dst, const void* gsrc) {
    asm volatile("cp.async.cg.shared.global [%0], [%1], 16;" :: "r"(smem_dst), "l"(gsrc));
}
#define CP_COMMIT() asm volatile("cp.async.commit_group;" ::: "memory")
#define CP_WAIT0()  asm volatile("cp.async.wait_group 0;" ::: "memory")

__device__ __forceinline__ float ex2f(float x) {
    float y; asm("ex2.approx.f32 %0, %1;" : "=f"(y) : "f"(x)); return y;
}
__device__ __forceinline__ float lg2f(float x) {
    float y; asm("lg2.approx.f32 %0, %1;" : "=f"(y) : "f"(x)); return y;
}
__device__ __forceinline__ void ldsm_x4(uint32_t& r0, uint32_t& r1, uint32_t& r2,
                                        uint32_t& r3, uint32_t addr) {
    asm volatile("ldmatrix.sync.aligned.m8n8.x4.shared.b16 {%0,%1,%2,%3}, [%4];"
                 : "=r"(r0), "=r"(r1), "=r"(r2), "=r"(r3) : "r"(addr));
}
__device__ __forceinline__ void mma16816(float* c, const uint32_t* a, const uint32_t* b) {
    asm volatile(
        "mma.sync.aligned.m16n8k16.row.col.f32.bf16.bf16.f32 "
        "{%0,%1,%2,%3}, {%4,%5,%6,%7}, {%8,%9}, {%0,%1,%2,%3};"
        : "+f"(c[0]), "+f"(c[1]), "+f"(c[2]), "+f"(c[3])
        : "r"(a[0]), "r"(a[1]), "r"(a[2]), "r"(a[3]), "r"(b[0]), "r"(b[1]));
}

// ---------------------------------------------------------------------------
// Kernel A: normalize rows, scale by sqrt(10*log2e), emit bf16. Warp per row.
// ---------------------------------------------------------------------------
__global__ __launch_bounds__(256) void normalize_kernel(
    const float* __restrict__ z1, const float* __restrict__ z2)
{
    const int wid = threadIdx.x >> 5, lid = threadIdx.x & 31;
    const int row = blockIdx.x * 8 + wid;
    const float* src = (row < HN) ? (z1 + (size_t)row * DD)
                                  : (z2 + (size_t)(row - HN) * DD);
    float4 v0 = reinterpret_cast<const float4*>(src)[lid];
    float4 v1 = reinterpret_cast<const float4*>(src)[lid + 32];
    float ss = v0.x * v0.x + v0.y * v0.y + v0.z * v0.z + v0.w * v0.w
             + v1.x * v1.x + v1.y * v1.y + v1.z * v1.z + v1.w * v1.w;
    #pragma unroll
    for (int off = 16; off > 0; off >>= 1) ss += __shfl_xor_sync(0xffffffffu, ss, off);
    float s = C_SCALE / fmaxf(sqrtf(ss), 1e-12f);
    __nv_bfloat162* dst = reinterpret_cast<__nv_bfloat162*>(g_zb + (size_t)row * DD);
    dst[2 * lid + 0]      = __floats2bfloat162_rn(v0.x * s, v0.y * s);
    dst[2 * lid + 1]      = __floats2bfloat162_rn(v0.z * s, v0.w * s);
    dst[64 + 2 * lid + 0] = __floats2bfloat162_rn(v1.x * s, v1.y * s);
    dst[64 + 2 * lid + 1] = __floats2bfloat162_rn(v1.z * s, v1.w * s);
}

// ---------------------------------------------------------------------------
// Kernel B: triangle-tile HMMA GEMM + fused ex2 epilogue with row+col sums.
// 130 CTAs x 16 tiles. SMEM: A resident 64KB + B double 128KB + reduce 3KB.
// ---------------------------------------------------------------------------
__global__ __launch_bounds__(256, 1) void sim_mma_kernel()
{
    extern __shared__ char smem[];
    const uint32_t sb = smem_u32(smem);
    const uint32_t A_BASE = sb, B_BASE = sb + 65536, BSZ = 65536;
    float* rowred = reinterpret_cast<float*>(smem + 196608);   // [2][128]
    float* colred = reinterpret_cast<float*>(smem + 197632);   // [4][128]

    const int tid = threadIdx.x, wid = tid >> 5, lid = tid & 31;
    const int wy = wid >> 1, wx = wid & 1;       // warp grid 4 (m) x 2 (n)
    const int my = wy * 32, nx = wx * 64;

    // find first tile (I,J) for flat index f0 = 16*blockIdx.x
    const int f0 = blockIdx.x * TPC;
    int I = 0, S = 0;
    while (S + (NBLK - I) <= f0) { S += NBLK - I; ++I; }
    int J = I + (f0 - S);

    // per-lane ldmatrix address components
    const int sub = lid >> 3, lr = lid & 7;
    const int rowA0 = my + ((sub & 1) << 3) + lr;
    const int cAoff = sub >> 1;
    const int rowB0 = nx + ((sub >> 1) << 3) + lr;
    const int cBoff = sub & 1;

    int curI = -1, bufc = 0;
    bool pend = false;

    for (int t = 0; t < TPC; ++t) {
        if (!pend) {
            if (t) __syncthreads();              // protect A / B-buf reuse
            if (I != curI) {
                for (int i = tid; i < 4096; i += 256) {
                    int r = i >> 5, c = i & 31;
                    cp16(A_BASE + r * 512 + ((c ^ (r & 7)) << 4),
                         &g_zb[(size_t)(I * 128 + r) * DD + c * 8]);
                }
                curI = I;
            }
            for (int i = tid; i < 4096; i += 256) {
                int r = i >> 5, c = i & 31;
                cp16(B_BASE + bufc * BSZ + r * 512 + ((c ^ (r & 7)) << 4),
                     &g_zb[(size_t)(J * 128 + r) * DD + c * 8]);
            }
            CP_COMMIT();
        }
        CP_WAIT0();
        __syncthreads();

        // prefetch next tile's B if same I
        int nI = I, nJ = J + 1;
        if (nJ == NBLK) { ++nI; nJ = nI; }
        if (t + 1 < TPC && nI == I) {
            for (int i = tid; i < 4096; i += 256) {
                int r = i >> 5, c = i & 31;
                cp16(B_BASE + (bufc ^ 1) * BSZ + r * 512 + ((c ^ (r & 7)) << 4),
                     &g_zb[(size_t)(nJ * 128 + r) * DD + c * 8]);
            }
            CP_COMMIT();
            pend = true;
        } else pend = false;

        // ---- GEMM 128x128x256 ----
        const uint32_t Bb = B_BASE + bufc * BSZ;
        float acc[2][8][4];
        #pragma unroll
        for (int i = 0; i < 2; ++i)
            #pragma unroll
            for (int j = 0; j < 8; ++j)
                #pragma unroll
                for (int q = 0; q < 4; ++q) acc[i][j][q] = 0.f;

        #pragma unroll
        for (int ks = 0; ks < 16; ++ks) {
            const int c0 = 2 * ks;
            uint32_t a[2][4], b[8][2];
            #pragma unroll
            for (int i = 0; i < 2; ++i) {
                int row = rowA0 + 16 * i;
                ldsm_x4(a[i][0], a[i][1], a[i][2], a[i][3],
                        A_BASE + row * 512 + (((c0 + cAoff) ^ (row & 7)) << 4));
            }
            #pragma unroll
            for (int jj = 0; jj < 4; ++jj) {
                int row = rowB0 + 16 * jj;
                ldsm_x4(b[2 * jj][0], b[2 * jj][1], b[2 * jj + 1][0], b[2 * jj + 1][1],
                        Bb + row * 512 + (((c0 + cBoff) ^ (row & 7)) << 4));
            }
            #pragma unroll
            for (int i = 0; i < 2; ++i)
                #pragma unroll
                for (int j = 0; j < 8; ++j)
                    mma16816(acc[i][j], a[i], b[j]);
        }

        // ---- epilogue: ex2, row sums (block I) + col sums (block J) ----
        const bool diag  = (I == J);
        const bool postl = (J == I + 32) && (I < 32);
        float re[4] = {0.f, 0.f, 0.f, 0.f};
        float cs[16];
        #pragma unroll
        for (int k = 0; k < 16; ++k) cs[k] = 0.f;

        if (diag) {
            const int colT = J * 128 + nx + 2 * (lid & 3);
            #pragma unroll
            for (int i = 0; i < 2; ++i) {
                const int gr0 = I * 128 + my + 16 * i + (lid >> 2);
                const int gr1 = gr0 + 8;
                #pragma unroll
                for (int j = 0; j < 8; ++j) {
                    const int gc0 = colT + 8 * j, gc1 = gc0 + 1;
                    if (gc0 != gr0) re[2 * i]     += ex2f(acc[i][j][0]);
                    if (gc1 != gr0) re[2 * i]     += ex2f(acc[i][j][1]);
                    if (gc0 != gr1) re[2 * i + 1] += ex2f(acc[i][j][2]);
                    if (gc1 != gr1) re[2 * i + 1] += ex2f(acc[i][j][3]);
                }
            }
        } else if (postl) {
            const int colT = J * 128 + nx + 2 * (lid & 3);
            #pragma unroll
            for (int i = 0; i < 2; ++i) {
                const int gr0 = I * 128 + my + 16 * i + (lid >> 2);
                const int gr1 = gr0 + 8;
                const int p0 = gr0 ^ HN, p1 = gr1 ^ HN;
                #pragma unroll
                for (int j = 0; j < 8; ++j) {
                    const int gc0 = colT + 8 * j, gc1 = gc0 + 1;
                    float e0 = ex2f(acc[i][j][0]), e1 = ex2f(acc[i][j][1]);
                    float e2 = ex2f(acc[i][j][2]), e3 = ex2f(acc[i][j][3]);
                    re[2 * i]     += e0 + e1;
                    re[2 * i + 1] += e2 + e3;
                    cs[2 * j]     += e0 + e2;
                    cs[2 * j + 1] += e1 + e3;
                    if (gc0 == p0) { g_posacc[gr0] = acc[i][j][0]; g_posacc[p0] = acc[i][j][0]; }
                    if (gc1 == p0) { g_posacc[gr0] = acc[i][j][1]; g_posacc[p0] = acc[i][j][1]; }
                    if (gc0 == p1) { g_posacc[gr1] = acc[i][j][2]; g_posacc[p1] = acc[i][j][2]; }
                    if (gc1 == p1) { g_posacc[gr1] = acc[i][j][3]; g_posacc[p1] = acc[i][j][3]; }
                }
            }
        } else {
            #pragma unroll
            for (int i = 0; i < 2; ++i)
                #pragma unroll
                for (int j = 0; j < 8; ++j) {
                    float e0 = ex2f(acc[i][j][0]), e1 = ex2f(acc[i][j][1]);
                    float e2 = ex2f(acc[i][j][2]), e3 = ex2f(acc[i][j][3]);
                    re[2 * i]     += e0 + e1;
                    re[2 * i + 1] += e2 + e3;
                    cs[2 * j]     += e0 + e2;
                    cs[2 * j + 1] += e1 + e3;
                }
        }

        // row sums: reduce lanes sharing a row (quad), write rowred
        #pragma unroll
        for (int e = 0; e < 4; ++e) {
            re[e] += __shfl_xor_sync(0xffffffffu, re[e], 1);
            re[e] += __shfl_xor_sync(0xffffffffu, re[e], 2);
        }
        if ((lid & 3) == 0) {
            #pragma unroll
            for (int e = 0; e < 4; ++e) {
                int rl = my + 16 * (e >> 1) + 8 * (e & 1) + (lid >> 2);
                rowred[wx * 128 + rl] = re[e];
            }
        }
        // col sums: reduce lanes sharing a col set (bits 2..4), write colred
        if (!diag) {
            #pragma unroll
            for (int k = 0; k < 16; ++k) {
                cs[k] += __shfl_xor_sync(0xffffffffu, cs[k], 4);
                cs[k] += __shfl_xor_sync(0xffffffffu, cs[k], 8);
                cs[k] += __shfl_xor_sync(0xffffffffu, cs[k], 16);
            }
            if (lid < 4) {
                #pragma unroll
                for (int k = 0; k < 16; ++k) {
                    int cl = nx + 8 * (k >> 1) + 2 * lid + (k & 1);
                    colred[wy * 128 + cl] = cs[k];
                }
            }
        }
        __syncthreads();
        const int f = f0 + t;
        if (tid < 128) {
            g_rowPart[(size_t)f * 128 + tid] = rowred[tid] + rowred[128 + tid];
            if (!diag)
                g_colPart[(size_t)f * 128 + tid] =
                    colred[tid] + colred[128 + tid] + colred[256 + tid] + colred[384 + tid];
        }

        if (pend) bufc ^= 1;
        I = nI; J = nJ;
    }
}

// ---------------------------------------------------------------------------
// Kernel C: per-row loss + global reduce; last-done block finalizes.
// grid 32 x 256 (one thread per row).
// ---------------------------------------------------------------------------
__global__ __launch_bounds__(256) void loss_reduce_kernel(float* __restrict__ out)
{
    const int r  = blockIdx.x * 256 + threadIdx.x;
    const int Ir = r >> 7, lr = r & 127;

    float tot = 0.f;
    // row-side partials: tiles (Ir, J), J = Ir..63
    const int base = NBLK * Ir - (Ir * (Ir - 1)) / 2;   // S(Ir)
    for (int Jt = Ir; Jt < NBLK; ++Jt)
        tot += g_rowPart[(size_t)(base + Jt - Ir) * 128 + lr];
    // col-side partials: tiles (I2, Ir), I2 = 0..Ir-1
    int Sp = 0;
    for (int I2 = 0; I2 < Ir; ++I2) {
        tot += g_colPart[(size_t)(Sp + Ir - I2) * 128 + lr];
        Sp += NBLK - I2;
    }
    float loss = lg2f(tot) - g_posacc[r];

    __shared__ float sm[256];
    __shared__ int last;
    sm[threadIdx.x] = loss;
    __syncthreads();
    #pragma unroll
    for (int off = 128; off > 0; off >>= 1) {
        if (threadIdx.x < off) sm[threadIdx.x] += sm[threadIdx.x + off];
        __syncthreads();
    }
    if (threadIdx.x == 0) {
        g_lossPartial[blockIdx.x] = sm[0];
        __threadfence();
        last = (atomicAdd(&g_ctr, 1) == 31);
    }
    __syncthreads();
    if (last && threadIdx.x < 32) {
        __threadfence();
        float v = g_lossPartial[threadIdx.x];
        #pragma unroll
        for (int off = 16; off > 0; off >>= 1)
            v += __shfl_down_sync(0xffffffffu, v, off);
        if (threadIdx.x == 0) { out[0] = v * (LN2 / (float)NN); g_ctr = 0; }
    }
}

// ---------------------------------------------------------------------------
extern "C" void kernel_launch(void* const* d_in, const int* in_sizes, int n_in,
                              void* d_out, int out_size)
{
    (void)in_sizes; (void)n_in; (void)out_size;
    const float* z1 = (const float*)d_in[0];
    const float* z2 = (const float*)d_in[1];
    float* out = (float*)d_out;

    static int smem_set = 0;
    const int SMEM_BYTES = 196608 + 3072;
    if (!smem_set) {
        cudaFuncSetAttribute(sim_mma_kernel,
                             cudaFuncAttributeMaxDynamicSharedMemorySize, SMEM_BYTES);
        smem_set = 1;
    }

    normalize_kernel<<<NN / 8, 256>>>(z1, z2);
    sim_mma_kernel<<<NCTA, 256, SMEM_BYTES>>>();
    loss_reduce_kernel<<<32, 256>>>(out);
}